// round 9
// baseline (speedup 1.0000x reference)
#include <cuda_runtime.h>
#include <math.h>

#define LSEQ   256
#define NN     608
#define DM     32
#define DI     64
#define DSTATE 16
#define NB     32
#define VV     19
#define NG     4
#define GS     4
#define PLANE  (LSEQ * NN * DI)

typedef unsigned long long ull;

// ---------------- packed fp32x2 helpers (sm_103a FFMA2 path) -----------------
__device__ __forceinline__ ull pack2(float x, float y) {
    ull r; asm("mov.b64 %0,{%1,%2};" : "=l"(r) : "f"(x), "f"(y)); return r;
}
__device__ __forceinline__ ull pack1(float x) {
    ull r; asm("mov.b64 %0,{%1,%1};" : "=l"(r) : "f"(x)); return r;
}
__device__ __forceinline__ void fma2(ull& d, ull a, ull b) {
    asm("fma.rn.f32x2 %0,%1,%2,%0;" : "+l"(d) : "l"(a), "l"(b));
}
__device__ __forceinline__ void unpk2(float& x, float& y, ull v) {
    asm("mov.b64 {%0,%1},%2;" : "=f"(x), "=f"(y) : "l"(v));
}

// ---------------- scratch (__device__ globals; no runtime allocs) ------------
__device__ float g_deg[NN];
__device__ float g_M[NN * VV];
__device__ float g_u [LSEQ * NN * DI];
__device__ float g_dt[LSEQ * NN * DI];
__device__ float g_sz[LSEQ * NN * DI];
__device__ float g_uB[LSEQ * NN * DI];
__device__ float g_Bm[LSEQ * NN * DSTATE];
__device__ float g_Cm[LSEQ * NN * DSTATE];
__device__ float g_yp[NG * PLANE];

// ---------------- degree (deterministic fixed-order reduction) ---------------
__global__ void k_deg(const int* __restrict__ ei, const float* __restrict__ ew, int E) {
    int v = blockIdx.x;
    if (threadIdx.x < VV) g_M[v * VV + threadIdx.x] = 0.f;
    float acc = 0.f;
    for (int e = threadIdx.x; e < E; e += 256)
        if (ei[E + e] == v) acc += ew[e];
    __shared__ float red[256];
    red[threadIdx.x] = acc;
    __syncthreads();
    for (int s = 128; s > 0; s >>= 1) {
        if (threadIdx.x < s) red[threadIdx.x] += red[threadIdx.x + s];
        __syncthreads();
    }
    if (threadIdx.x == 0) g_deg[v] = red[0] + 1.0f;
}

// ---------------- dense per-batch GCN norm matrix ---------------------------
__global__ void k_buildM(const int* __restrict__ ei, const float* __restrict__ ew, int E) {
    int i = blockIdx.x * 256 + threadIdx.x;
    if (i < E) {
        int s = ei[i], d = ei[E + i];
        int b = d / VV;
        int sl = s - b * VV;
        float ds = rsqrtf(fmaxf(g_deg[s], 1e-12f));
        float dd = rsqrtf(fmaxf(g_deg[d], 1e-12f));
        g_M[d * VV + sl] = ew[i] * ds * dd;
    } else if (i < E + NN) {
        int v = i - E;
        int vl = v % VV;
        float di = rsqrtf(fmaxf(g_deg[v], 1e-12f));
        g_M[v * VV + vl] = di * di;
    }
}

// ---------------- fused prep: projections + uB precompute --------------------
#define PREP_SMEM_FLOATS (9728 + 9728 + 2176 + 4160 + 361 + 304 + 128 + 64 + 64)
#define PREP_SMEM_BYTES  (PREP_SMEM_FLOATS * 4)

__global__ void __launch_bounds__(256) k_prep(
    const float* __restrict__ x_in, const float* __restrict__ ipw,
    const float* __restrict__ xpw,  const float* __restrict__ dtw,
    const float* __restrict__ dtb,  const float* __restrict__ gBw,
    const float* __restrict__ gBb) {
    extern __shared__ float sm[];
    float* regA = sm;                    // sxin first 4864, later sh (9728)
    float* su   = regA + 9728;
    float* sxpw = su + 9728;
    float* sWt  = sxpw + 2176;
    float* sM   = sWt + 4160;
    float* sdtr = sM + 361;
    float* sdtw = sdtr + 304;
    float* sdtb = sdtw + 128;
    float* sgBb = sdtb + 64;

    int b  = blockIdx.x;
    int t0 = blockIdx.y * 8;
    int tid = threadIdx.x;

    for (int idx = tid; idx < 8 * VV * DM; idx += 256) {
        int t = idx / (VV * DM), r = idx - t * (VV * DM);
        int v = r / DM, m = r - v * DM;
        regA[idx] = x_in[((b * VV + v) * LSEQ + t0 + t) * DM + m];
    }
    for (int idx = tid; idx < 34 * DI; idx += 256) sxpw[idx] = xpw[idx];
    for (int idx = tid; idx < DI * DI; idx += 256) {
        int e = idx >> 6, d = idx & 63;
        sWt[d * 65 + e] = gBw[idx];
    }
    for (int idx = tid; idx < VV * VV; idx += 256) sM[idx] = g_M[(b * VV) * VV + idx];
    if (tid < 128) sdtw[tid] = dtw[tid];
    if (tid < 64)  { sdtb[tid] = dtb[tid]; sgBb[tid] = gBb[tid]; }

    int e_r = tid & 127;
    int th  = tid >> 7;
    float4 w8[8];
    const float4* ipw4 = (const float4*)ipw;
#pragma unroll
    for (int j = 0; j < 8; j++) w8[j] = ipw4[e_r * 8 + j];
    __syncthreads();

    for (int tt = 0; tt < 4; tt++) {
        int t = th * 4 + tt;
#pragma unroll 1
        for (int v = 0; v < VV; v++) {
            const float4* xx = (const float4*)(regA + t * (VV * DM) + v * DM);
            float acc = 0.f;
#pragma unroll
            for (int j = 0; j < 8; j++) {
                float4 a = xx[j];
                acc += w8[j].x * a.x + w8[j].y * a.y + w8[j].z * a.z + w8[j].w * a.w;
            }
            int base = ((t0 + t) * NN + b * VV + v) * DI;
            if (e_r < DI) {
                su[t * (VV * DI) + v * DI + e_r] = acc;
                g_u[base + e_r] = acc;
            } else {
                g_sz[base + (e_r - DI)] = acc / (1.f + __expf(-acc));
            }
        }
    }
    __syncthreads();

    for (int task = tid; task < 8 * VV * 34; task += 256) {
        int j = task % 34, r = task / 34;
        int t = r / VV, v = r - t * VV;
        const float4* xr = (const float4*)(su + t * (VV * DI) + v * DI);
        const float4* wr = (const float4*)(sxpw + j * DI);
        float acc = 0.f;
#pragma unroll
        for (int q = 0; q < 16; q++) {
            float4 a = xr[q], w = wr[q];
            acc += a.x * w.x + a.y * w.y + a.z * w.z + a.w * w.w;
        }
        int node = (t0 + t) * NN + b * VV + v;
        if (j < 2)       sdtr[r * 2 + j] = acc;
        else if (j < 18) g_Bm[node * DSTATE + (j - 2)]  = acc;
        else             g_Cm[node * DSTATE + (j - 18)] = acc;
    }
    __syncthreads();

    for (int task = tid; task < 8 * VV * DI; task += 256) {
        int d = task & 63, r = task >> 6;
        int t = r / VV, v = r - t * VV;
        float xv = sdtw[d * 2] * sdtr[r * 2] + sdtw[d * 2 + 1] * sdtr[r * 2 + 1] + sdtb[d];
        g_dt[((t0 + t) * NN + b * VV + v) * DI + d] = (xv > 20.f) ? xv : log1pf(expf(xv));
    }

    for (int task = tid; task < 8 * VV * DI; task += 256) {
        int e = task & 63, r = task >> 6;
        int t = r / VV, v = r - t * VV;
        const float* ur = su + t * (VV * DI) + v * DI;
        float acc = 0.f;
#pragma unroll 8
        for (int d = 0; d < DI; d++) acc += ur[d] * sWt[d * 65 + e];
        regA[t * (VV * DI) + v * DI + e] = acc;
    }
    __syncthreads();

    for (int task = tid; task < 8 * VV * DI; task += 256) {
        int e = task & 63, r = task >> 6;
        int t = r / VV, v = r - t * VV;
        float acc = sgBb[e];
        const float* Mr = sM + v * VV;
        const float* hb = regA + t * (VV * DI) + e;
#pragma unroll
        for (int i = 0; i < VV; i++) acc += Mr[i] * hb[i * DI];
        g_uB[((t0 + t) * NN + b * VV + v) * DI + e] = acc;
    }
}

// ---------------- persistent scan: one CTA per (n-group, batch) --------------
// floats: WtA 4096 | WtC 4096 | Ae 256 | sSt 4940 | sHA 4864 | sHC 4864
//         | sM2 380 ull = 760 | bA 64 | bC 64  = 24004 floats
#define SCAN_SMEM_BYTES (24008 * 4)

__global__ void __launch_bounds__(608, 1) k_scan(
    const float* __restrict__ gAw, const float* __restrict__ gAb,
    const float* __restrict__ gCw, const float* __restrict__ gCb,
    const float* __restrict__ A_log) {
    extern __shared__ float smem[];
    float* sWtA = smem;                 // [d*64+e] = WA[e][d]
    float* sWtC = sWtA + 4096;
    float* sAe  = sWtC + 4096;          // [e*4+n]
    float* sSt  = sAe + 256;            // [vv*260 + d*4 + n]
    float* sHA  = sSt + 4940;           // [i*256 + e*4 + n]  (hA for next step)
    float* sHC  = sHA + 4864;           //                    (hC for this step)
    ull*   sM2  = (ull*)(sHC + 4864);   // rows padded to 20 ull, dup pairs
    float* sbA  = (float*)(sM2 + 380);
    float* sbC  = sbA + 64;

    int gi  = blockIdx.x;
    int b   = blockIdx.y;
    int tid = threadIdx.x;              // 608 = 19 warps

    for (int idx = tid; idx < 4096; idx += 608) {
        int d = idx >> 6, e = idx & 63;
        sWtA[idx] = gAw[e * DI + d];
        sWtC[idx] = gCw[e * DI + d];
    }
    for (int idx = tid; idx < VV * VV; idx += 608)
        sM2[(idx / VV) * 20 + idx % VV] = pack1(g_M[(b * VV) * VV + idx]);
    if (tid < 64) { sbA[tid] = gAb[tid]; sbC[tid] = gCb[tid]; }
    for (int idx = tid; idx < 256; idx += 608) {
        int e = idx >> 2, j = idx & 3;
        sAe[idx] = -expf(A_log[e * DSTATE + gi * GS + j]);
    }
    for (int idx = tid; idx < 4864; idx += 608) sHA[idx] = 0.f;  // hA(0) = WA@0
    __syncthreads();

    const ulonglong2* sSt2 = (const ulonglong2*)sSt;  // (vv*65 + d)
    ull* sHA2 = (ull*)sHA;                            // (i*128 + c7)
    ull* sHC2 = (ull*)sHC;

    const int iv = tid >> 5;            // transform: vertex
    const int eb = tid & 31;            // transform: e lane (e=eb, e=eb+32)

    // update/output mapping: 512 threads = 4 vv-groups x 64 e x 2 n-halves
    const bool act = tid < 512;
    const int c7  = tid & 127;          // = e2*2 + hf
    const int e2  = c7 >> 1, hf = c7 & 1;
    const int grp = (tid >> 7) & 3;
    const int vvs = grp * 5;
    const int nvv = (grp < 3) ? 5 : 4;
    float aE0 = 0.f, aE1 = 0.f, bAv = 0.f, bCv = 0.f;
    if (act) {
        aE0 = sAe[e2 * 4 + hf * 2];
        aE1 = sAe[e2 * 4 + hf * 2 + 1];
        bAv = sbA[e2]; bCv = sbC[e2];
    }

    // prefetch inputs for t = 0
    float dtv[5], ubv[5]; float2 Bv[5];
    if (act) {
#pragma unroll
        for (int k = 0; k < 5; k++) if (k < nvv) {
            int node = b * VV + vvs + k;
            dtv[k] = g_dt[node * DI + e2];
            ubv[k] = g_uB[node * DI + e2];
            Bv[k]  = *(const float2*)&g_Bm[node * DSTATE + gi * GS + hf * 2];
        }
    }

    for (int t = 0; t < LSEQ; t++) {
        // ---------- interval 1: U(t) then Y(t-1) ----------
        if (act) {
            float2 Cy[5];
            if (t > 0) {
                int pbase = (t - 1) * NN + b * VV;
#pragma unroll
                for (int k = 0; k < 5; k++) if (k < nvv)
                    Cy[k] = *(const float2*)&g_Cm[(pbase + vvs + k) * DSTATE + gi * GS + hf * 2];
            }
            // U(t): s(t) = (M@hA + bA) * exp(dt*A) + (uB*dt)*B
            {
                ull Hc[VV];
#pragma unroll
                for (int i = 0; i < VV; i++) Hc[i] = sHA2[i * 128 + c7];
#pragma unroll
                for (int k = 0; k < 5; k++) if (k < nvv) {
                    int vv = vvs + k;
                    ull acc = pack2(bAv, bAv);
                    const ulonglong2* Mp = (const ulonglong2*)(sM2 + vv * 20);
#pragma unroll
                    for (int i2 = 0; i2 < 9; i2++) {
                        ulonglong2 m = Mp[i2];
                        fma2(acc, m.x, Hc[2 * i2]);
                        fma2(acc, m.y, Hc[2 * i2 + 1]);
                    }
                    fma2(acc, sM2[vv * 20 + 18], Hc[18]);
                    float a0, a1; unpk2(a0, a1, acc);
                    float dv = dtv[k], cb = ubv[k] * dv;
                    float s0 = a0 * __expf(dv * aE0) + cb * Bv[k].x;
                    float s1 = a1 * __expf(dv * aE1) + cb * Bv[k].y;
                    *(float2*)&sSt[vv * 260 + e2 * 4 + hf * 2] = make_float2(s0, s1);
                }
            }
            // Y(t-1): y = sum_n (M@hC + bC) * C
            if (t > 0) {
                int pbase = (t - 1) * NN + b * VV;
                ull Hc[VV];
#pragma unroll
                for (int i = 0; i < VV; i++) Hc[i] = sHC2[i * 128 + c7];
#pragma unroll
                for (int k = 0; k < 5; k++) if (k < nvv) {
                    int vv = vvs + k;
                    ull acc = pack2(bCv, bCv);
                    const ulonglong2* Mp = (const ulonglong2*)(sM2 + vv * 20);
#pragma unroll
                    for (int i2 = 0; i2 < 9; i2++) {
                        ulonglong2 m = Mp[i2];
                        fma2(acc, m.x, Hc[2 * i2]);
                        fma2(acc, m.y, Hc[2 * i2 + 1]);
                    }
                    fma2(acc, sM2[vv * 20 + 18], Hc[18]);
                    float a0, a1; unpk2(a0, a1, acc);
                    float yv = a0 * Cy[k].x + a1 * Cy[k].y;
                    yv += __shfl_xor_sync(0xffffffffu, yv, 1);
                    if (hf == 0)
                        g_yp[gi * PLANE + (pbase + vv) * DI + e2] = yv;
                }
            }
        }
        __syncthreads();

        // ---------- interval 2: prefetch(t+1) + fused transform T(t) ----------
        if (act && t + 1 < LSEQ) {
            int nb2 = (t + 1) * NN + b * VV;
#pragma unroll
            for (int k = 0; k < 5; k++) if (k < nvv) {
                int node = nb2 + vvs + k;
                dtv[k] = g_dt[node * DI + e2];
                ubv[k] = g_uB[node * DI + e2];
                Bv[k]  = *(const float2*)&g_Bm[node * DSTATE + gi * GS + hf * 2];
            }
        }
        {
            ull aA0 = 0, aA1 = 0, aA2 = 0, aA3 = 0;
            ull aC0 = 0, aC1 = 0, aC2 = 0, aC3 = 0;
#pragma unroll 16
            for (int d = 0; d < DI; d++) {
                ulonglong2 s2 = sSt2[iv * 65 + d];       // warp broadcast
                ull wA0 = pack1(sWtA[d * 64 + eb]);
                ull wA1 = pack1(sWtA[d * 64 + eb + 32]);
                ull wC0 = pack1(sWtC[d * 64 + eb]);
                ull wC1 = pack1(sWtC[d * 64 + eb + 32]);
                fma2(aA0, wA0, s2.x); fma2(aA1, wA0, s2.y);
                fma2(aA2, wA1, s2.x); fma2(aA3, wA1, s2.y);
                fma2(aC0, wC0, s2.x); fma2(aC1, wC0, s2.y);
                fma2(aC2, wC1, s2.x); fma2(aC3, wC1, s2.y);
            }
            ulonglong2 v;
            v.x = aA0; v.y = aA1; *(ulonglong2*)&sHA2[iv * 128 + eb * 2]      = v;
            v.x = aA2; v.y = aA3; *(ulonglong2*)&sHA2[iv * 128 + 64 + eb * 2] = v;
            v.x = aC0; v.y = aC1; *(ulonglong2*)&sHC2[iv * 128 + eb * 2]      = v;
            v.x = aC2; v.y = aC3; *(ulonglong2*)&sHC2[iv * 128 + 64 + eb * 2] = v;
        }
        __syncthreads();
    }

    // ---------- epilogue: Y(255) ----------
    if (act) {
        int pbase = (LSEQ - 1) * NN + b * VV;
        float2 Cy[5];
#pragma unroll
        for (int k = 0; k < 5; k++) if (k < nvv)
            Cy[k] = *(const float2*)&g_Cm[(pbase + vvs + k) * DSTATE + gi * GS + hf * 2];
        ull Hc[VV];
#pragma unroll
        for (int i = 0; i < VV; i++) Hc[i] = sHC2[i * 128 + c7];
#pragma unroll
        for (int k = 0; k < 5; k++) if (k < nvv) {
            int vv = vvs + k;
            ull acc = pack2(bCv, bCv);
            const ulonglong2* Mp = (const ulonglong2*)(sM2 + vv * 20);
#pragma unroll
            for (int i2 = 0; i2 < 9; i2++) {
                ulonglong2 m = Mp[i2];
                fma2(acc, m.x, Hc[2 * i2]);
                fma2(acc, m.y, Hc[2 * i2 + 1]);
            }
            fma2(acc, sM2[vv * 20 + 18], Hc[18]);
            float a0, a1; unpk2(a0, a1, acc);
            float yv = a0 * Cy[k].x + a1 * Cy[k].y;
            yv += __shfl_xor_sync(0xffffffffu, yv, 1);
            if (hf == 0)
                g_yp[gi * PLANE + (pbase + vv) * DI + e2] = yv;
        }
    }
}

// ---------------- epilogue: y = (sum_g yp + D*u) * silu(z); out = y @ Wout^T -
__global__ void __launch_bounds__(256) k_out(const float* __restrict__ Dp,
                                             const float* __restrict__ opw,
                                             float* __restrict__ out) {
    int v = blockIdx.x, t0 = blockIdx.y * 16;
    int tid = threadIdx.x;
    __shared__ __align__(16) float sy [16 * DI];
    __shared__ __align__(16) float sow[DM * DI];
    for (int idx = tid; idx < DM * DI; idx += 256) sow[idx] = opw[idx];
    for (int task = tid; task < 16 * DI; task += 256) {
        int p = task >> 6, e = task & 63;
        int idx = ((t0 + p) * NN + v) * DI + e;
        float a = g_yp[idx] + g_yp[PLANE + idx] + g_yp[2 * PLANE + idx]
                + g_yp[3 * PLANE + idx];
        sy[task] = (a + Dp[e] * g_u[idx]) * g_sz[idx];
    }
    __syncthreads();
    for (int task = tid; task < 16 * DM; task += 256) {
        int p = task >> 5, m = task & 31;
        const float4* yr = (const float4*)(sy + p * DI);
        const float4* wr = (const float4*)(sow + m * DI);
        float acc = 0.f;
#pragma unroll
        for (int q = 0; q < 16; q++) {
            float4 a = yr[q], w = wr[q];
            acc += a.x * w.x + a.y * w.y + a.z * w.z + a.w * w.w;
        }
        out[(v * LSEQ + t0 + p) * DM + m] = acc;
    }
}

// ---------------- launch -----------------------------------------------------
extern "C" void kernel_launch(void* const* d_in, const int* in_sizes, int n_in,
                              void* d_out, int out_size) {
    const float* x_in  = (const float*)d_in[0];
    const int*   ei    = (const int*)  d_in[1];
    const float* ew    = (const float*)d_in[2];
    const float* ipw   = (const float*)d_in[3];
    const float* xpw   = (const float*)d_in[4];
    const float* dtw   = (const float*)d_in[5];
    const float* dtb   = (const float*)d_in[6];
    const float* A_log = (const float*)d_in[7];
    const float* Dp    = (const float*)d_in[8];
    const float* opw   = (const float*)d_in[9];
    const float* gAw   = (const float*)d_in[10];
    const float* gAb   = (const float*)d_in[11];
    const float* gBw   = (const float*)d_in[12];
    const float* gBb   = (const float*)d_in[13];
    const float* gCw   = (const float*)d_in[14];
    const float* gCb   = (const float*)d_in[15];
    float* out = (float*)d_out;
    int E = in_sizes[2];

    k_deg<<<NN, 256>>>(ei, ew, E);
    k_buildM<<<(E + NN + 255) / 256, 256>>>(ei, ew, E);
    cudaFuncSetAttribute(k_prep, cudaFuncAttributeMaxDynamicSharedMemorySize,
                         PREP_SMEM_BYTES);
    k_prep<<<dim3(NB, LSEQ / 8), 256, PREP_SMEM_BYTES>>>(x_in, ipw, xpw, dtw,
                                                         dtb, gBw, gBb);
    cudaFuncSetAttribute(k_scan, cudaFuncAttributeMaxDynamicSharedMemorySize,
                         SCAN_SMEM_BYTES);
    k_scan<<<dim3(NG, NB), 608, SCAN_SMEM_BYTES>>>(gAw, gAb, gCw, gCb, A_log);
    k_out<<<dim3(NN, LSEQ / 16), 256>>>(Dp, opw, out);
}

// round 11
// speedup vs baseline: 1.0753x; 1.0753x over previous
#include <cuda_runtime.h>
#include <math.h>

#define LSEQ   256
#define NN     608
#define DM     32
#define DI     64
#define DSTATE 16
#define NB     32
#define VV     19
#define NG     4
#define GS     4
#define PLANE  (LSEQ * NN * DI)

typedef unsigned long long ull;

// ---------------- packed fp32x2 helpers (sm_103a FFMA2 path) -----------------
__device__ __forceinline__ ull pack2(float x, float y) {
    ull r; asm("mov.b64 %0,{%1,%2};" : "=l"(r) : "f"(x), "f"(y)); return r;
}
__device__ __forceinline__ ull pack1(float x) {
    ull r; asm("mov.b64 %0,{%1,%1};" : "=l"(r) : "f"(x)); return r;
}
__device__ __forceinline__ void fma2(ull& d, ull a, ull b) {
    asm("fma.rn.f32x2 %0,%1,%2,%0;" : "+l"(d) : "l"(a), "l"(b));
}
__device__ __forceinline__ void unpk2(float& x, float& y, ull v) {
    asm("mov.b64 {%0,%1},%2;" : "=f"(x), "=f"(y) : "l"(v));
}

// ---------------- scratch (__device__ globals; no runtime allocs) ------------
__device__ float g_deg[NN];
__device__ float g_M[NN * VV];
__device__ float g_u [LSEQ * NN * DI];
__device__ float g_dt[LSEQ * NN * DI];
__device__ float g_sz[LSEQ * NN * DI];
__device__ float g_uB[LSEQ * NN * DI];
__device__ float g_Bm[LSEQ * NN * DSTATE];
__device__ float g_Cm[LSEQ * NN * DSTATE];
__device__ float g_yp[NG * PLANE];

// ---------------- degree (deterministic fixed-order reduction) ---------------
__global__ void k_deg(const int* __restrict__ ei, const float* __restrict__ ew, int E) {
    int v = blockIdx.x;
    if (threadIdx.x < VV) g_M[v * VV + threadIdx.x] = 0.f;
    float acc = 0.f;
    for (int e = threadIdx.x; e < E; e += 256)
        if (ei[E + e] == v) acc += ew[e];
    __shared__ float red[256];
    red[threadIdx.x] = acc;
    __syncthreads();
    for (int s = 128; s > 0; s >>= 1) {
        if (threadIdx.x < s) red[threadIdx.x] += red[threadIdx.x + s];
        __syncthreads();
    }
    if (threadIdx.x == 0) g_deg[v] = red[0] + 1.0f;
}

// ---------------- dense per-batch GCN norm matrix ---------------------------
__global__ void k_buildM(const int* __restrict__ ei, const float* __restrict__ ew, int E) {
    int i = blockIdx.x * 256 + threadIdx.x;
    if (i < E) {
        int s = ei[i], d = ei[E + i];
        int b = d / VV;
        int sl = s - b * VV;
        float ds = rsqrtf(fmaxf(g_deg[s], 1e-12f));
        float dd = rsqrtf(fmaxf(g_deg[d], 1e-12f));
        g_M[d * VV + sl] = ew[i] * ds * dd;
    } else if (i < E + NN) {
        int v = i - E;
        int vl = v % VV;
        float di = rsqrtf(fmaxf(g_deg[v], 1e-12f));
        g_M[v * VV + vl] = di * di;
    }
}

// ---------------- fused prep: projections + uB precompute --------------------
#define PREP_SMEM_FLOATS (9728 + 9728 + 2176 + 4160 + 361 + 304 + 128 + 64 + 64)
#define PREP_SMEM_BYTES  (PREP_SMEM_FLOATS * 4)

__global__ void __launch_bounds__(256) k_prep(
    const float* __restrict__ x_in, const float* __restrict__ ipw,
    const float* __restrict__ xpw,  const float* __restrict__ dtw,
    const float* __restrict__ dtb,  const float* __restrict__ gBw,
    const float* __restrict__ gBb) {
    extern __shared__ float sm[];
    float* regA = sm;                    // sxin first 4864, later sh (9728)
    float* su   = regA + 9728;
    float* sxpw = su + 9728;
    float* sWt  = sxpw + 2176;
    float* sM   = sWt + 4160;
    float* sdtr = sM + 361;
    float* sdtw = sdtr + 304;
    float* sdtb = sdtw + 128;
    float* sgBb = sdtb + 64;

    int b  = blockIdx.x;
    int t0 = blockIdx.y * 8;
    int tid = threadIdx.x;

    for (int idx = tid; idx < 8 * VV * DM; idx += 256) {
        int t = idx / (VV * DM), r = idx - t * (VV * DM);
        int v = r / DM, m = r - v * DM;
        regA[idx] = x_in[((b * VV + v) * LSEQ + t0 + t) * DM + m];
    }
    for (int idx = tid; idx < 34 * DI; idx += 256) sxpw[idx] = xpw[idx];
    for (int idx = tid; idx < DI * DI; idx += 256) {
        int e = idx >> 6, d = idx & 63;
        sWt[d * 65 + e] = gBw[idx];
    }
    for (int idx = tid; idx < VV * VV; idx += 256) sM[idx] = g_M[(b * VV) * VV + idx];
    if (tid < 128) sdtw[tid] = dtw[tid];
    if (tid < 64)  { sdtb[tid] = dtb[tid]; sgBb[tid] = gBb[tid]; }

    int e_r = tid & 127;
    int th  = tid >> 7;
    float4 w8[8];
    const float4* ipw4 = (const float4*)ipw;
#pragma unroll
    for (int j = 0; j < 8; j++) w8[j] = ipw4[e_r * 8 + j];
    __syncthreads();

    for (int tt = 0; tt < 4; tt++) {
        int t = th * 4 + tt;
#pragma unroll 1
        for (int v = 0; v < VV; v++) {
            const float4* xx = (const float4*)(regA + t * (VV * DM) + v * DM);
            float acc = 0.f;
#pragma unroll
            for (int j = 0; j < 8; j++) {
                float4 a = xx[j];
                acc += w8[j].x * a.x + w8[j].y * a.y + w8[j].z * a.z + w8[j].w * a.w;
            }
            int base = ((t0 + t) * NN + b * VV + v) * DI;
            if (e_r < DI) {
                su[t * (VV * DI) + v * DI + e_r] = acc;
                g_u[base + e_r] = acc;
            } else {
                g_sz[base + (e_r - DI)] = acc / (1.f + __expf(-acc));
            }
        }
    }
    __syncthreads();

    for (int task = tid; task < 8 * VV * 34; task += 256) {
        int j = task % 34, r = task / 34;
        int t = r / VV, v = r - t * VV;
        const float4* xr = (const float4*)(su + t * (VV * DI) + v * DI);
        const float4* wr = (const float4*)(sxpw + j * DI);
        float acc = 0.f;
#pragma unroll
        for (int q = 0; q < 16; q++) {
            float4 a = xr[q], w = wr[q];
            acc += a.x * w.x + a.y * w.y + a.z * w.z + a.w * w.w;
        }
        int node = (t0 + t) * NN + b * VV + v;
        if (j < 2)       sdtr[r * 2 + j] = acc;
        else if (j < 18) g_Bm[node * DSTATE + (j - 2)]  = acc;
        else             g_Cm[node * DSTATE + (j - 18)] = acc;
    }
    __syncthreads();

    for (int task = tid; task < 8 * VV * DI; task += 256) {
        int d = task & 63, r = task >> 6;
        int t = r / VV, v = r - t * VV;
        float xv = sdtw[d * 2] * sdtr[r * 2] + sdtw[d * 2 + 1] * sdtr[r * 2 + 1] + sdtb[d];
        g_dt[((t0 + t) * NN + b * VV + v) * DI + d] = (xv > 20.f) ? xv : log1pf(expf(xv));
    }

    for (int task = tid; task < 8 * VV * DI; task += 256) {
        int e = task & 63, r = task >> 6;
        int t = r / VV, v = r - t * VV;
        const float* ur = su + t * (VV * DI) + v * DI;
        float acc = 0.f;
#pragma unroll 8
        for (int d = 0; d < DI; d++) acc += ur[d] * sWt[d * 65 + e];
        regA[t * (VV * DI) + v * DI + e] = acc;
    }
    __syncthreads();

    for (int task = tid; task < 8 * VV * DI; task += 256) {
        int e = task & 63, r = task >> 6;
        int t = r / VV, v = r - t * VV;
        float acc = sgBb[e];
        const float* Mr = sM + v * VV;
        const float* hb = regA + t * (VV * DI) + e;
#pragma unroll
        for (int i = 0; i < VV; i++) acc += Mr[i] * hb[i * DI];
        g_uB[((t0 + t) * NN + b * VV + v) * DI + e] = acc;
    }
}

// ---------------- persistent scan: one CTA per (n-group, batch) --------------
// floats: WtA 4096 | WtC 4096 | Ae 256 | sSt 4940 | sHA 4864 | sHC 4864
//         | sM2 380 ull = 760 | bA 64 | bC 64  = 24004 floats
#define SCAN_SMEM_BYTES (24008 * 4)

__global__ void __launch_bounds__(608, 1) k_scan(
    const float* __restrict__ gAw, const float* __restrict__ gAb,
    const float* __restrict__ gCw, const float* __restrict__ gCb,
    const float* __restrict__ A_log) {
    extern __shared__ float smem[];
    float* sWtA = smem;                 // [d*64+e] = WA[e][d]
    float* sWtC = sWtA + 4096;
    float* sAe  = sWtC + 4096;          // [e*4+n]
    float* sSt  = sAe + 256;            // [vv*260 + d*4 + n]
    float* sHA  = sSt + 4940;           // [i*256 + e*4 + n]  (hA feeding U(t+1))
    float* sHC  = sHA + 4864;           // (hC feeding Y(t))
    ull*   sM2  = (ull*)(sHC + 4864);   // rows padded to 20 ull, dup pairs
    float* sbA  = (float*)(sM2 + 380);
    float* sbC  = sbA + 64;

    int gi  = blockIdx.x;
    int b   = blockIdx.y;
    int tid = threadIdx.x;              // 608 = 19 warps

    for (int idx = tid; idx < 4096; idx += 608) {
        int d = idx >> 6, e = idx & 63;
        sWtA[idx] = gAw[e * DI + d];
        sWtC[idx] = gCw[e * DI + d];
    }
    for (int idx = tid; idx < VV * VV; idx += 608)
        sM2[(idx / VV) * 20 + idx % VV] = pack1(g_M[(b * VV) * VV + idx]);
    if (tid < 64) { sbA[tid] = gAb[tid]; sbC[tid] = gCb[tid]; }
    for (int idx = tid; idx < 256; idx += 608) {
        int e = idx >> 2, j = idx & 3;
        sAe[idx] = -expf(A_log[e * DSTATE + gi * GS + j]);
    }
    for (int idx = tid; idx < 4864; idx += 608) sHA[idx] = 0.f;  // hA(0) = WA@0
    __syncthreads();

    const ulonglong2* sSt2 = (const ulonglong2*)sSt;  // (vv*65 + d)
    ull* sHA2 = (ull*)sHA;                            // (i*128 + c7)
    ull* sHC2 = (ull*)sHC;

    const int iv = tid >> 5;            // transform: vertex
    const int eb = tid & 31;            // transform: e lane (e=eb, e=eb+32)

    // update/output mapping: 512 threads = 4 vv-groups x 64 e x 2 n-halves
    const bool act = tid < 512;
    const int c7  = tid & 127;          // = e2*2 + hf
    const int e2  = c7 >> 1, hf = c7 & 1;
    const int grp = (tid >> 7) & 3;
    const int vvs = grp * 5;
    const int nvv = (grp < 3) ? 5 : 4;
    float aE0 = 0.f, aE1 = 0.f, bAv = 0.f, bCv = 0.f;
    if (act) {
        aE0 = sAe[e2 * 4 + hf * 2];
        aE1 = sAe[e2 * 4 + hf * 2 + 1];
        bAv = sbA[e2]; bCv = sbC[e2];
    }

    // prefetch inputs for t = 0
    float dtv[5], ubv[5]; float2 Bv[5];
    if (act) {
#pragma unroll
        for (int k = 0; k < 5; k++) if (k < nvv) {
            int node = b * VV + vvs + k;
            dtv[k] = g_dt[node * DI + e2];
            ubv[k] = g_uB[node * DI + e2];
            Bv[k]  = *(const float2*)&g_Bm[node * DSTATE + gi * GS + hf * 2];
        }
    }

    for (int t = 0; t < LSEQ; t++) {
        // ---------- interval 1: U(t) then Y(t-1) ----------
        if (act) {
            // U(t): s(t) = (M@hA + bA) * exp(dt*A) + (uB*dt)*B
            {
                ull Hc[VV];
#pragma unroll
                for (int i = 0; i < VV; i++) Hc[i] = sHA2[i * 128 + c7];
#pragma unroll
                for (int k = 0; k < 5; k++) if (k < nvv) {
                    int vv = vvs + k;
                    ull acc = pack2(bAv, bAv);
                    const ulonglong2* Mp = (const ulonglong2*)(sM2 + vv * 20);
#pragma unroll
                    for (int i2 = 0; i2 < 9; i2++) {
                        ulonglong2 m = Mp[i2];
                        fma2(acc, m.x, Hc[2 * i2]);
                        fma2(acc, m.y, Hc[2 * i2 + 1]);
                    }
                    fma2(acc, sM2[vv * 20 + 18], Hc[18]);
                    float a0, a1; unpk2(a0, a1, acc);
                    float dv = dtv[k], cb = ubv[k] * dv;
                    float s0 = a0 * __expf(dv * aE0) + cb * Bv[k].x;
                    float s1 = a1 * __expf(dv * aE1) + cb * Bv[k].y;
                    *(float2*)&sSt[vv * 260 + e2 * 4 + hf * 2] = make_float2(s0, s1);
                }
            }
            // Y(t-1): y = sum_n (M@hC + bC) * C   (Cy loaded after U frees regs)
            if (t > 0) {
                int pbase = (t - 1) * NN + b * VV;
                float2 Cy[5];
#pragma unroll
                for (int k = 0; k < 5; k++) if (k < nvv)
                    Cy[k] = *(const float2*)&g_Cm[(pbase + vvs + k) * DSTATE + gi * GS + hf * 2];
                ull Hc[VV];
#pragma unroll
                for (int i = 0; i < VV; i++) Hc[i] = sHC2[i * 128 + c7];
#pragma unroll
                for (int k = 0; k < 5; k++) if (k < nvv) {
                    int vv = vvs + k;
                    ull acc = pack2(bCv, bCv);
                    const ulonglong2* Mp = (const ulonglong2*)(sM2 + vv * 20);
#pragma unroll
                    for (int i2 = 0; i2 < 9; i2++) {
                        ulonglong2 m = Mp[i2];
                        fma2(acc, m.x, Hc[2 * i2]);
                        fma2(acc, m.y, Hc[2 * i2 + 1]);
                    }
                    fma2(acc, sM2[vv * 20 + 18], Hc[18]);
                    float a0, a1; unpk2(a0, a1, acc);
                    float yv = a0 * Cy[k].x + a1 * Cy[k].y;
                    yv += __shfl_xor_sync(0xffffffffu, yv, 1);
                    if (hf == 0)
                        g_yp[gi * PLANE + (pbase + vv) * DI + e2] = yv;
                }
            }
        }
        __syncthreads();

        // ---------- interval 2: prefetch(t+1), then C-pass and A-pass ----------
        if (act && t + 1 < LSEQ) {
            int nb2 = (t + 1) * NN + b * VV;
#pragma unroll
            for (int k = 0; k < 5; k++) if (k < nvv) {
                int node = nb2 + vvs + k;
                dtv[k] = g_dt[node * DI + e2];
                ubv[k] = g_uB[node * DI + e2];
                Bv[k]  = *(const float2*)&g_Bm[node * DSTATE + gi * GS + hf * 2];
            }
        }
        // C-pass: hC = WC @ s(t)
        {
            ull a0 = 0, a1 = 0, a2 = 0, a3 = 0;
#pragma unroll 8
            for (int d = 0; d < DI; d++) {
                ulonglong2 s2 = sSt2[iv * 65 + d];       // warp broadcast
                ull w0 = pack1(sWtC[d * 64 + eb]);
                ull w1 = pack1(sWtC[d * 64 + eb + 32]);
                fma2(a0, w0, s2.x); fma2(a1, w0, s2.y);
                fma2(a2, w1, s2.x); fma2(a3, w1, s2.y);
            }
            ulonglong2 v;
            v.x = a0; v.y = a1; *(ulonglong2*)&sHC2[iv * 128 + eb * 2]      = v;
            v.x = a2; v.y = a3; *(ulonglong2*)&sHC2[iv * 128 + 64 + eb * 2] = v;
        }
        // A-pass: hA = WA @ s(t)
        {
            ull a0 = 0, a1 = 0, a2 = 0, a3 = 0;
#pragma unroll 8
            for (int d = 0; d < DI; d++) {
                ulonglong2 s2 = sSt2[iv * 65 + d];
                ull w0 = pack1(sWtA[d * 64 + eb]);
                ull w1 = pack1(sWtA[d * 64 + eb + 32]);
                fma2(a0, w0, s2.x); fma2(a1, w0, s2.y);
                fma2(a2, w1, s2.x); fma2(a3, w1, s2.y);
            }
            ulonglong2 v;
            v.x = a0; v.y = a1; *(ulonglong2*)&sHA2[iv * 128 + eb * 2]      = v;
            v.x = a2; v.y = a3; *(ulonglong2*)&sHA2[iv * 128 + 64 + eb * 2] = v;
        }
        __syncthreads();
    }

    // ---------- epilogue: Y(255) ----------
    if (act) {
        int pbase = (LSEQ - 1) * NN + b * VV;
        float2 Cy[5];
#pragma unroll
        for (int k = 0; k < 5; k++) if (k < nvv)
            Cy[k] = *(const float2*)&g_Cm[(pbase + vvs + k) * DSTATE + gi * GS + hf * 2];
        ull Hc[VV];
#pragma unroll
        for (int i = 0; i < VV; i++) Hc[i] = sHC2[i * 128 + c7];
#pragma unroll
        for (int k = 0; k < 5; k++) if (k < nvv) {
            int vv = vvs + k;
            ull acc = pack2(bCv, bCv);
            const ulonglong2* Mp = (const ulonglong2*)(sM2 + vv * 20);
#pragma unroll
            for (int i2 = 0; i2 < 9; i2++) {
                ulonglong2 m = Mp[i2];
                fma2(acc, m.x, Hc[2 * i2]);
                fma2(acc, m.y, Hc[2 * i2 + 1]);
            }
            fma2(acc, sM2[vv * 20 + 18], Hc[18]);
            float a0, a1; unpk2(a0, a1, acc);
            float yv = a0 * Cy[k].x + a1 * Cy[k].y;
            yv += __shfl_xor_sync(0xffffffffu, yv, 1);
            if (hf == 0)
                g_yp[gi * PLANE + (pbase + vv) * DI + e2] = yv;
        }
    }
}

// ---------------- epilogue: y = (sum_g yp + D*u) * silu(z); out = y @ Wout^T -
__global__ void __launch_bounds__(256) k_out(const float* __restrict__ Dp,
                                             const float* __restrict__ opw,
                                             float* __restrict__ out) {
    int v = blockIdx.x, t0 = blockIdx.y * 16;
    int tid = threadIdx.x;
    __shared__ __align__(16) float sy [16 * DI];
    __shared__ __align__(16) float sow[DM * DI];
    for (int idx = tid; idx < DM * DI; idx += 256) sow[idx] = opw[idx];
    for (int task = tid; task < 16 * DI; task += 256) {
        int p = task >> 6, e = task & 63;
        int idx = ((t0 + p) * NN + v) * DI + e;
        float a = g_yp[idx] + g_yp[PLANE + idx] + g_yp[2 * PLANE + idx]
                + g_yp[3 * PLANE + idx];
        sy[task] = (a + Dp[e] * g_u[idx]) * g_sz[idx];
    }
    __syncthreads();
    for (int task = tid; task < 16 * DM; task += 256) {
        int p = task >> 5, m = task & 31;
        const float4* yr = (const float4*)(sy + p * DI);
        const float4* wr = (const float4*)(sow + m * DI);
        float acc = 0.f;
#pragma unroll
        for (int q = 0; q < 16; q++) {
            float4 a = yr[q], w = wr[q];
            acc += a.x * w.x + a.y * w.y + a.z * w.z + a.w * w.w;
        }
        out[(v * LSEQ + t0 + p) * DM + m] = acc;
    }
}

// ---------------- launch -----------------------------------------------------
extern "C" void kernel_launch(void* const* d_in, const int* in_sizes, int n_in,
                              void* d_out, int out_size) {
    const float* x_in  = (const float*)d_in[0];
    const int*   ei    = (const int*)  d_in[1];
    const float* ew    = (const float*)d_in[2];
    const float* ipw   = (const float*)d_in[3];
    const float* xpw   = (const float*)d_in[4];
    const float* dtw   = (const float*)d_in[5];
    const float* dtb   = (const float*)d_in[6];
    const float* A_log = (const float*)d_in[7];
    const float* Dp    = (const float*)d_in[8];
    const float* opw   = (const float*)d_in[9];
    const float* gAw   = (const float*)d_in[10];
    const float* gAb   = (const float*)d_in[11];
    const float* gBw   = (const float*)d_in[12];
    const float* gBb   = (const float*)d_in[13];
    const float* gCw   = (const float*)d_in[14];
    const float* gCb   = (const float*)d_in[15];
    float* out = (float*)d_out;
    int E = in_sizes[2];

    k_deg<<<NN, 256>>>(ei, ew, E);
    k_buildM<<<(E + NN + 255) / 256, 256>>>(ei, ew, E);
    cudaFuncSetAttribute(k_prep, cudaFuncAttributeMaxDynamicSharedMemorySize,
                         PREP_SMEM_BYTES);
    k_prep<<<dim3(NB, LSEQ / 8), 256, PREP_SMEM_BYTES>>>(x_in, ipw, xpw, dtw,
                                                         dtb, gBw, gBb);
    cudaFuncSetAttribute(k_scan, cudaFuncAttributeMaxDynamicSharedMemorySize,
                         SCAN_SMEM_BYTES);
    k_scan<<<dim3(NG, NB), 608, SCAN_SMEM_BYTES>>>(gAw, gAb, gCw, gCb, A_log);
    k_out<<<dim3(NN, LSEQ / 16), 256>>>(Dp, opw, out);
}

// round 12
// speedup vs baseline: 1.6046x; 1.4923x over previous
#include <cuda_runtime.h>
#include <math.h>

#define LSEQ   256
#define NN     608
#define DM     32
#define DI     64
#define DSTATE 16
#define NB     32
#define VV     19
#define NG     4
#define GS     4
#define PLANE  (LSEQ * NN * DI)

typedef unsigned long long ull;

// ---------------- packed fp32x2 helpers (sm_103a FFMA2 path) -----------------
__device__ __forceinline__ ull pack2(float x, float y) {
    ull r; asm("mov.b64 %0,{%1,%2};" : "=l"(r) : "f"(x), "f"(y)); return r;
}
__device__ __forceinline__ ull pack1(float x) {
    ull r; asm("mov.b64 %0,{%1,%1};" : "=l"(r) : "f"(x)); return r;
}
__device__ __forceinline__ void fma2(ull& d, ull a, ull b) {
    asm("fma.rn.f32x2 %0,%1,%2,%0;" : "+l"(d) : "l"(a), "l"(b));
}
__device__ __forceinline__ void unpk2(float& x, float& y, ull v) {
    asm("mov.b64 {%0,%1},%2;" : "=f"(x), "=f"(y) : "l"(v));
}

// ---------------- scratch (__device__ globals; no runtime allocs) ------------
__device__ float g_deg[NN];
__device__ float g_M[NN * VV];
__device__ float g_u [LSEQ * NN * DI];
__device__ float g_dt[LSEQ * NN * DI];
__device__ float g_sz[LSEQ * NN * DI];
__device__ float g_uB[LSEQ * NN * DI];
__device__ float g_Bm[LSEQ * NN * DSTATE];
__device__ float g_Cm[LSEQ * NN * DSTATE];
__device__ float g_yp[NG * PLANE];

// ---------------- degree (deterministic fixed-order reduction) ---------------
__global__ void k_deg(const int* __restrict__ ei, const float* __restrict__ ew, int E) {
    int v = blockIdx.x;
    if (threadIdx.x < VV) g_M[v * VV + threadIdx.x] = 0.f;
    float acc = 0.f;
    for (int e = threadIdx.x; e < E; e += 256)
        if (ei[E + e] == v) acc += ew[e];
    __shared__ float red[256];
    red[threadIdx.x] = acc;
    __syncthreads();
    for (int s = 128; s > 0; s >>= 1) {
        if (threadIdx.x < s) red[threadIdx.x] += red[threadIdx.x + s];
        __syncthreads();
    }
    if (threadIdx.x == 0) g_deg[v] = red[0] + 1.0f;
}

// ---------------- dense per-batch GCN norm matrix ---------------------------
__global__ void k_buildM(const int* __restrict__ ei, const float* __restrict__ ew, int E) {
    int i = blockIdx.x * 256 + threadIdx.x;
    if (i < E) {
        int s = ei[i], d = ei[E + i];
        int b = d / VV;
        int sl = s - b * VV;
        float ds = rsqrtf(fmaxf(g_deg[s], 1e-12f));
        float dd = rsqrtf(fmaxf(g_deg[d], 1e-12f));
        g_M[d * VV + sl] = ew[i] * ds * dd;
    } else if (i < E + NN) {
        int v = i - E;
        int vl = v % VV;
        float di = rsqrtf(fmaxf(g_deg[v], 1e-12f));
        g_M[v * VV + vl] = di * di;
    }
}

// ---------------- fused prep: projections + uB precompute --------------------
#define PREP_SMEM_FLOATS (9728 + 9728 + 2176 + 4160 + 361 + 304 + 128 + 64 + 64)
#define PREP_SMEM_BYTES  (PREP_SMEM_FLOATS * 4)

__global__ void __launch_bounds__(256) k_prep(
    const float* __restrict__ x_in, const float* __restrict__ ipw,
    const float* __restrict__ xpw,  const float* __restrict__ dtw,
    const float* __restrict__ dtb,  const float* __restrict__ gBw,
    const float* __restrict__ gBb) {
    extern __shared__ float sm[];
    float* regA = sm;                    // sxin first 4864, later sh (9728)
    float* su   = regA + 9728;
    float* sxpw = su + 9728;
    float* sWt  = sxpw + 2176;
    float* sM   = sWt + 4160;
    float* sdtr = sM + 361;
    float* sdtw = sdtr + 304;
    float* sdtb = sdtw + 128;
    float* sgBb = sdtb + 64;

    int b  = blockIdx.x;
    int t0 = blockIdx.y * 8;
    int tid = threadIdx.x;

    for (int idx = tid; idx < 8 * VV * DM; idx += 256) {
        int t = idx / (VV * DM), r = idx - t * (VV * DM);
        int v = r / DM, m = r - v * DM;
        regA[idx] = x_in[((b * VV + v) * LSEQ + t0 + t) * DM + m];
    }
    for (int idx = tid; idx < 34 * DI; idx += 256) sxpw[idx] = xpw[idx];
    for (int idx = tid; idx < DI * DI; idx += 256) {
        int e = idx >> 6, d = idx & 63;
        sWt[d * 65 + e] = gBw[idx];
    }
    for (int idx = tid; idx < VV * VV; idx += 256) sM[idx] = g_M[(b * VV) * VV + idx];
    if (tid < 128) sdtw[tid] = dtw[tid];
    if (tid < 64)  { sdtb[tid] = dtb[tid]; sgBb[tid] = gBb[tid]; }

    int e_r = tid & 127;
    int th  = tid >> 7;
    float4 w8[8];
    const float4* ipw4 = (const float4*)ipw;
#pragma unroll
    for (int j = 0; j < 8; j++) w8[j] = ipw4[e_r * 8 + j];
    __syncthreads();

    for (int tt = 0; tt < 4; tt++) {
        int t = th * 4 + tt;
#pragma unroll 1
        for (int v = 0; v < VV; v++) {
            const float4* xx = (const float4*)(regA + t * (VV * DM) + v * DM);
            float acc = 0.f;
#pragma unroll
            for (int j = 0; j < 8; j++) {
                float4 a = xx[j];
                acc += w8[j].x * a.x + w8[j].y * a.y + w8[j].z * a.z + w8[j].w * a.w;
            }
            int base = ((t0 + t) * NN + b * VV + v) * DI;
            if (e_r < DI) {
                su[t * (VV * DI) + v * DI + e_r] = acc;
                g_u[base + e_r] = acc;
            } else {
                g_sz[base + (e_r - DI)] = acc / (1.f + __expf(-acc));
            }
        }
    }
    __syncthreads();

    for (int task = tid; task < 8 * VV * 34; task += 256) {
        int j = task % 34, r = task / 34;
        int t = r / VV, v = r - t * VV;
        const float4* xr = (const float4*)(su + t * (VV * DI) + v * DI);
        const float4* wr = (const float4*)(sxpw + j * DI);
        float acc = 0.f;
#pragma unroll
        for (int q = 0; q < 16; q++) {
            float4 a = xr[q], w = wr[q];
            acc += a.x * w.x + a.y * w.y + a.z * w.z + a.w * w.w;
        }
        int node = (t0 + t) * NN + b * VV + v;
        if (j < 2)       sdtr[r * 2 + j] = acc;
        else if (j < 18) g_Bm[node * DSTATE + (j - 2)]  = acc;
        else             g_Cm[node * DSTATE + (j - 18)] = acc;
    }
    __syncthreads();

    for (int task = tid; task < 8 * VV * DI; task += 256) {
        int d = task & 63, r = task >> 6;
        int t = r / VV, v = r - t * VV;
        float xv = sdtw[d * 2] * sdtr[r * 2] + sdtw[d * 2 + 1] * sdtr[r * 2 + 1] + sdtb[d];
        g_dt[((t0 + t) * NN + b * VV + v) * DI + d] = (xv > 20.f) ? xv : log1pf(expf(xv));
    }

    for (int task = tid; task < 8 * VV * DI; task += 256) {
        int e = task & 63, r = task >> 6;
        int t = r / VV, v = r - t * VV;
        const float* ur = su + t * (VV * DI) + v * DI;
        float acc = 0.f;
#pragma unroll 8
        for (int d = 0; d < DI; d++) acc += ur[d] * sWt[d * 65 + e];
        regA[t * (VV * DI) + v * DI + e] = acc;
    }
    __syncthreads();

    for (int task = tid; task < 8 * VV * DI; task += 256) {
        int e = task & 63, r = task >> 6;
        int t = r / VV, v = r - t * VV;
        float acc = sgBb[e];
        const float* Mr = sM + v * VV;
        const float* hb = regA + t * (VV * DI) + e;
#pragma unroll
        for (int i = 0; i < VV; i++) acc += Mr[i] * hb[i * DI];
        g_uB[((t0 + t) * NN + b * VV + v) * DI + e] = acc;
    }
}

// ---------------- persistent scan: one CTA per (n-group, batch) --------------
// R8 4-phase structure (no spills) + vertex-paired transforms (phases 1/3).
// smem floats: WtA 4096 | WtC 4096 | Ae 256 | sSt 4940 | sH 4864
//              | sM2 722 (ull dup) | bA 64 | bC 64  = 19102
#define SCAN_SMEM_BYTES (19104 * 4)

__global__ void __launch_bounds__(608, 1) k_scan(
    const float* __restrict__ gAw, const float* __restrict__ gAb,
    const float* __restrict__ gCw, const float* __restrict__ gCb,
    const float* __restrict__ A_log) {
    extern __shared__ float smem[];
    float* sWtA = smem;                 // [d*64+e] = WA[e][d]
    float* sWtC = sWtA + 4096;
    float* sAe  = sWtC + 4096;          // [e*4+n]
    float* sSt  = sAe + 256;            // [vv*260 + d*4 + n]
    float* sH   = sSt + 4940;           // [i*256 + e*4 + n]
    ull*   sM2  = (ull*)(sH + 4864);    // 361 duplicated pairs
    float* sbA  = (float*)(sM2 + 361);
    float* sbC  = sbA + 64;

    int gi  = blockIdx.x;
    int b   = blockIdx.y;
    int tid = threadIdx.x;              // 608 = 19 warps

    for (int idx = tid; idx < 4096; idx += 608) {
        int d = idx >> 6, e = idx & 63;
        sWtA[idx] = gAw[e * DI + d];
        sWtC[idx] = gCw[e * DI + d];
    }
    for (int idx = tid; idx < VV * VV; idx += 608)
        sM2[idx] = pack1(g_M[(b * VV) * VV + idx]);
    if (tid < 64) { sbA[tid] = gAb[tid]; sbC[tid] = gCb[tid]; }
    for (int idx = tid; idx < 256; idx += 608) {
        int e = idx >> 2, j = idx & 3;
        sAe[idx] = -expf(A_log[e * DSTATE + gi * GS + j]);
    }
    for (int idx = tid; idx < 4940; idx += 608) sSt[idx] = 0.f;
    __syncthreads();

    const ulonglong2* sSt2 = (const ulonglong2*)sSt;  // idx (vv*65 + d)
    ull* sH2 = (ull*)sH;                              // idx (i*128 + e*2 + hf)

    // transform mapping: 10 warps x 2 vertices (warp 9 has only v=18)
    const int eb = tid & 31;            // e lane: e=eb and e=eb+32
    const int tw = tid >> 5;            // warp id
    const bool tact = tw < 10;
    const int v0 = tw * 2;
    const bool hasv1 = (v0 + 1) < VV;
    const int v1 = hasv1 ? v0 + 1 : v0;

    // update/output mapping: 512 threads = 4 vv-groups x 64 e x 2 n-halves
    const bool act = tid < 512;
    const int c7  = tid & 127;          // = e2*2 + hf
    const int e2  = c7 >> 1, hf = c7 & 1;
    const int grp = (tid >> 7) & 3;
    const int vvs = grp * 5;
    const int nvv = (grp < 3) ? 5 : 4;
    float aE0 = 0.f, aE1 = 0.f, bAv = 0.f, bCv = 0.f;
    if (act) {
        aE0 = sAe[e2 * 4 + hf * 2];
        aE1 = sAe[e2 * 4 + hf * 2 + 1];
        bAv = sbA[e2]; bCv = sbC[e2];
    }

    for (int t = 0; t < LSEQ; t++) {
        int nbase = t * NN + b * VV;

        // hoisted global loads (latency hidden under phase 1)
        float dtv[5], ubv[5];
        float2 B2[5], C2[5];
        if (act) {
#pragma unroll
            for (int k = 0; k < 5; k++) {
                if (k < nvv) {
                    int node = nbase + vvs + k;
                    dtv[k] = g_dt[node * DI + e2];
                    ubv[k] = g_uB[node * DI + e2];
                    B2[k]  = *(const float2*)&g_Bm[node * DSTATE + gi * GS + hf * 2];
                    C2[k]  = *(const float2*)&g_Cm[node * DSTATE + gi * GS + hf * 2];
                }
            }
        }

        // phase 1: hA = WA @ s, two vertices per warp (weights loaded once)
        if (tact) {
            ull a0 = 0, a1 = 0, a2 = 0, a3 = 0;
            ull c0 = 0, c1 = 0, c2 = 0, c3 = 0;
#pragma unroll 8
            for (int d = 0; d < DI; d++) {
                ulonglong2 s0 = sSt2[v0 * 65 + d];       // warp broadcast
                ulonglong2 s1 = sSt2[v1 * 65 + d];
                ull w0 = pack1(sWtA[d * 64 + eb]);
                ull w1 = pack1(sWtA[d * 64 + eb + 32]);
                fma2(a0, w0, s0.x); fma2(a1, w0, s0.y);
                fma2(a2, w1, s0.x); fma2(a3, w1, s0.y);
                fma2(c0, w0, s1.x); fma2(c1, w0, s1.y);
                fma2(c2, w1, s1.x); fma2(c3, w1, s1.y);
            }
            ulonglong2 v;
            v.x = a0; v.y = a1; *(ulonglong2*)&sH2[v0 * 128 + eb * 2]      = v;
            v.x = a2; v.y = a3; *(ulonglong2*)&sH2[v0 * 128 + 64 + eb * 2] = v;
            if (hasv1) {
                v.x = c0; v.y = c1; *(ulonglong2*)&sH2[v1 * 128 + eb * 2]      = v;
                v.x = c2; v.y = c3; *(ulonglong2*)&sH2[v1 * 128 + 64 + eb * 2] = v;
            }
        }
        __syncthreads();

        // phase 2: sA = M@hA + bA ; s_new = sA*exp(dt*A) + (uB*dt)*B
        if (act) {
            ull Hc[VV];
#pragma unroll
            for (int i = 0; i < VV; i++) Hc[i] = sH2[i * 128 + c7];
#pragma unroll
            for (int k = 0; k < 5; k++) {
                if (k < nvv) {
                    int vv = vvs + k;
                    ull acc = pack2(bAv, bAv);
                    const ull* M2r = sM2 + vv * VV;
#pragma unroll
                    for (int i = 0; i < VV; i++) fma2(acc, M2r[i], Hc[i]);
                    float a0, a1; unpk2(a0, a1, acc);
                    float dv = dtv[k], cb = ubv[k] * dv;
                    float s0 = a0 * __expf(dv * aE0) + cb * B2[k].x;
                    float s1 = a1 * __expf(dv * aE1) + cb * B2[k].y;
                    *(float2*)&sSt[vv * 260 + e2 * 4 + hf * 2] = make_float2(s0, s1);
                }
            }
        }
        __syncthreads();

        // phase 3: hC = WC @ s_new, vertex-paired
        if (tact) {
            ull a0 = 0, a1 = 0, a2 = 0, a3 = 0;
            ull c0 = 0, c1 = 0, c2 = 0, c3 = 0;
#pragma unroll 8
            for (int d = 0; d < DI; d++) {
                ulonglong2 s0 = sSt2[v0 * 65 + d];
                ulonglong2 s1 = sSt2[v1 * 65 + d];
                ull w0 = pack1(sWtC[d * 64 + eb]);
                ull w1 = pack1(sWtC[d * 64 + eb + 32]);
                fma2(a0, w0, s0.x); fma2(a1, w0, s0.y);
                fma2(a2, w1, s0.x); fma2(a3, w1, s0.y);
                fma2(c0, w0, s1.x); fma2(c1, w0, s1.y);
                fma2(c2, w1, s1.x); fma2(c3, w1, s1.y);
            }
            ulonglong2 v;
            v.x = a0; v.y = a1; *(ulonglong2*)&sH2[v0 * 128 + eb * 2]      = v;
            v.x = a2; v.y = a3; *(ulonglong2*)&sH2[v0 * 128 + 64 + eb * 2] = v;
            if (hasv1) {
                v.x = c0; v.y = c1; *(ulonglong2*)&sH2[v1 * 128 + eb * 2]      = v;
                v.x = c2; v.y = c3; *(ulonglong2*)&sH2[v1 * 128 + 64 + eb * 2] = v;
            }
        }
        __syncthreads();

        // phase 4: sC = M@hC + bC ; y_part = sum_n sC*C (pair + 1 shfl)
        if (act) {
            ull Hc[VV];
#pragma unroll
            for (int i = 0; i < VV; i++) Hc[i] = sH2[i * 128 + c7];
#pragma unroll
            for (int k = 0; k < 5; k++) {
                if (k < nvv) {
                    int vv = vvs + k;
                    ull acc = pack2(bCv, bCv);
                    const ull* M2r = sM2 + vv * VV;
#pragma unroll
                    for (int i = 0; i < VV; i++) fma2(acc, M2r[i], Hc[i]);
                    float a0, a1; unpk2(a0, a1, acc);
                    float yv = a0 * C2[k].x + a1 * C2[k].y;
                    yv += __shfl_xor_sync(0xffffffffu, yv, 1);
                    if (hf == 0)
                        g_yp[gi * PLANE + (nbase + vv) * DI + e2] = yv;
                }
            }
        }
        __syncthreads();
    }
}

// ---------------- epilogue: y = (sum_g yp + D*u) * silu(z); out = y @ Wout^T -
__global__ void __launch_bounds__(256) k_out(const float* __restrict__ Dp,
                                             const float* __restrict__ opw,
                                             float* __restrict__ out) {
    int v = blockIdx.x, t0 = blockIdx.y * 16;
    int tid = threadIdx.x;
    __shared__ __align__(16) float sy [16 * DI];
    __shared__ __align__(16) float sow[DM * DI];
    for (int idx = tid; idx < DM * DI; idx += 256) sow[idx] = opw[idx];
    for (int task = tid; task < 16 * DI; task += 256) {
        int p = task >> 6, e = task & 63;
        int idx = ((t0 + p) * NN + v) * DI + e;
        float a = g_yp[idx] + g_yp[PLANE + idx] + g_yp[2 * PLANE + idx]
                + g_yp[3 * PLANE + idx];
        sy[task] = (a + Dp[e] * g_u[idx]) * g_sz[idx];
    }
    __syncthreads();
    for (int task = tid; task < 16 * DM; task += 256) {
        int p = task >> 5, m = task & 31;
        const float4* yr = (const float4*)(sy + p * DI);
        const float4* wr = (const float4*)(sow + m * DI);
        float acc = 0.f;
#pragma unroll
        for (int q = 0; q < 16; q++) {
            float4 a = yr[q], w = wr[q];
            acc += a.x * w.x + a.y * w.y + a.z * w.z + a.w * w.w;
        }
        out[(v * LSEQ + t0 + p) * DM + m] = acc;
    }
}

// ---------------- launch -----------------------------------------------------
extern "C" void kernel_launch(void* const* d_in, const int* in_sizes, int n_in,
                              void* d_out, int out_size) {
    const float* x_in  = (const float*)d_in[0];
    const int*   ei    = (const int*)  d_in[1];
    const float* ew    = (const float*)d_in[2];
    const float* ipw   = (const float*)d_in[3];
    const float* xpw   = (const float*)d_in[4];
    const float* dtw   = (const float*)d_in[5];
    const float* dtb   = (const float*)d_in[6];
    const float* A_log = (const float*)d_in[7];
    const float* Dp    = (const float*)d_in[8];
    const float* opw   = (const float*)d_in[9];
    const float* gAw   = (const float*)d_in[10];
    const float* gAb   = (const float*)d_in[11];
    const float* gBw   = (const float*)d_in[12];
    const float* gBb   = (const float*)d_in[13];
    const float* gCw   = (const float*)d_in[14];
    const float* gCb   = (const float*)d_in[15];
    float* out = (float*)d_out;
    int E = in_sizes[2];

    k_deg<<<NN, 256>>>(ei, ew, E);
    k_buildM<<<(E + NN + 255) / 256, 256>>>(ei, ew, E);
    cudaFuncSetAttribute(k_prep, cudaFuncAttributeMaxDynamicSharedMemorySize,
                         PREP_SMEM_BYTES);
    k_prep<<<dim3(NB, LSEQ / 8), 256, PREP_SMEM_BYTES>>>(x_in, ipw, xpw, dtw,
                                                         dtb, gBw, gBb);
    cudaFuncSetAttribute(k_scan, cudaFuncAttributeMaxDynamicSharedMemorySize,
                         SCAN_SMEM_BYTES);
    k_scan<<<dim3(NG, NB), 608, SCAN_SMEM_BYTES>>>(gAw, gAb, gCw, gCb, A_log);
    k_out<<<dim3(NN, LSEQ / 16), 256>>>(Dp, opw, out);
}